// round 16
// baseline (speedup 1.0000x reference)
#include <cuda_runtime.h>
#include <cuda_fp16.h>
#include <cstdint>

// Problem constants
#define NN 50000
#define DD 128
#define EE 625000
#define PST 136          // padded row stride in halves (272 B) for ldmatrix

// Scratch (allocation-free rule: __device__ globals)
__device__ __half g_agg16[(size_t)NN * DD];
__device__ __half g_xh[(size_t)NN * DD];
__device__ __half g_hh[(size_t)NN * DD];
// Transposed fp16 weights, padded [128 n][PST k]:
// 0=W1_rel 1=W1_root 2=W2_rel 3=W2_root
__device__ __half g_wth[4 * 128 * PST];

// ---------------------------------------------------------------------------
// Fused prep: zero agg16 | x->xh fp16 convert | weight transpose->fp16.
// ---------------------------------------------------------------------------
#define PREP_Z   (NN * DD / 8)
#define PREP_C   (NN * DD / 4)
#define PREP_W   (4 * 128 * 128)
#define PREP_TOT (PREP_Z + PREP_C + PREP_W)

__global__ void prep_kernel(const float4* __restrict__ x,
                            const float* __restrict__ w0,
                            const float* __restrict__ w1,
                            const float* __restrict__ w2,
                            const float* __restrict__ w3,
                            uint4* __restrict__ aggz,
                            uint2* __restrict__ xh,
                            __half* __restrict__ wth) {
    int i = blockIdx.x * blockDim.x + threadIdx.x;
    if (i < PREP_Z) {
        aggz[i] = make_uint4(0, 0, 0, 0);
    } else if (i < PREP_Z + PREP_C) {
        int j = i - PREP_Z;
        float4 v = x[j];
        __half2 a = __floats2half2_rn(v.x, v.y);
        __half2 b = __floats2half2_rn(v.z, v.w);
        xh[j] = make_uint2(*(unsigned*)&a, *(unsigned*)&b);
    } else if (i < PREP_TOT) {
        int g = i - PREP_Z - PREP_C;
        int m = g >> 14, e = g & 16383;
        int n = e >> 7, k = e & 127;
        const float* W = (m == 0) ? w0 : (m == 1) ? w1 : (m == 2) ? w2 : w3;
        wth[m * 128 * PST + n * PST + k] = __float2half_rn(W[k * 128 + n]);
    }
}

// ---------------------------------------------------------------------------
// fp16 scatter-aggregate: half-warp per edge, 128-bit REDs, 16 edges/warp.
// ---------------------------------------------------------------------------
#define EPW 16
__global__ void scatter16_kernel(const __half* __restrict__ feat,
                                 const int* __restrict__ ei,
                                 __half* __restrict__ agg) {
    int gw = (blockIdx.x * blockDim.x + threadIdx.x) >> 5;
    int lane = threadIdx.x & 31;
    int half = lane >> 4;
    int hl = lane & 15;
    int e0 = gw * EPW;
    if (e0 >= EE) return;

    uint4 v[EPW / 2];
    int d[EPW / 2];
#pragma unroll
    for (int t = 0; t < EPW / 2; t++) {
        int e = e0 + 2 * t + half;
        if (e < EE) {
            int s = __ldg(&ei[e]);
            d[t] = __ldg(&ei[EE + e]);
            v[t] = ((const uint4*)(feat + (size_t)s * DD))[hl];
        }
    }
#pragma unroll
    for (int t = 0; t < EPW / 2; t++) {
        int e = e0 + 2 * t + half;
        if (e < EE) {
            const __half* dp = agg + (size_t)d[t] * DD + hl * 8;
            asm volatile("red.global.add.noftz.v4.f16x2 [%0], {%1, %2, %3, %4};"
                         :: "l"(dp), "r"(v[t].x), "r"(v[t].y),
                            "r"(v[t].z), "r"(v[t].w)
                         : "memory");
        }
    }
}

// ---------------------------------------------------------------------------
// Persistent MMA GEMM: out = act( agg@Wrel + X@Wroot + bias ).
// 2 fp16 HMMA passes: (agg, Wrel) (Xh, Wroot).
// grid = 296 (2 CTAs/SM); weights staged ONCE per CTA; tile loop over
// 64-row tiles. Smem: A(17408)+X(17408)+W0(34816)+W1(34816) = 104448 B.
// ---------------------------------------------------------------------------
#define GSM_A   0
#define GSM_XH  17408
#define GSM_W0  34816
#define GSM_W1  69632
#define GSMEM   104448
#define NTILES  ((NN + 63) / 64)     // 782
#define GGRID   296

__device__ __forceinline__ uint32_t smem_u32(const void* p) {
    uint32_t a;
    asm("{ .reg .u64 t; cvta.to.shared.u64 t, %1; cvt.u32.u64 %0, t; }"
        : "=r"(a) : "l"(p));
    return a;
}

__global__ __launch_bounds__(256, 2)
void gemm_mma_kernel(const __half* __restrict__ A16,
                     __half* __restrict__ aggz,       // to zero (or null)
                     const __half* __restrict__ Xh,
                     const __half* __restrict__ wth_rel,
                     const __half* __restrict__ wth_root,
                     const float* __restrict__ bias,
                     float* __restrict__ out32,       // fp32 out (or null)
                     __half* __restrict__ outh,       // fp16 out (or null)
                     int relu) {
    extern __shared__ char sm[];
    uint32_t sbase = smem_u32(sm);
    int tid = threadIdx.x, wid = tid >> 5, lane = tid & 31;

    // Stage both W tiles ONCE per CTA
    for (int i = tid; i < 2176; i += 256) {
        ((uint4*)(sm + GSM_W0))[i] = ((const uint4*)wth_rel)[i];
        ((uint4*)(sm + GSM_W1))[i] = ((const uint4*)wth_root)[i];
    }

    int rw = wid & 3;       // row-block (4 x 16 rows = 64)
    int cw = wid >> 2;      // col-block (2 x 64 cols = 128)

    int a_row  = rw * 16 + ((lane >> 3) & 1) * 8 + (lane & 7);
    int a_koff = (lane >> 4) * 8;
    uint32_t a_off = (uint32_t)(a_row * 272 + a_koff * 2);
    int b_mat = lane >> 3;
    int b_line = cw * 64 + ((b_mat >> 1) & 1) * 8 + (lane & 7);
    int b_koff = (b_mat & 1) * 8;
    uint32_t b_rel = (uint32_t)(b_line * 272 + b_koff * 2);

    const uint32_t aoff[2] = {GSM_A, GSM_XH};
    const uint32_t woff[2] = {GSM_W0, GSM_W1};

    for (int bt = blockIdx.x; bt < NTILES; bt += GGRID) {
        int row0 = bt * 64;

        __syncthreads();   // prior tile's readers done (and W ready on iter 0)
        // Stage A/X tiles: [64][PST]h (row pad 272 B)
        for (int w = tid; w < 64 * 16; w += 256) {
            int r = w >> 4, c = w & 15;
            int grow = row0 + r;
            uint4 va, vh;
            if (grow < NN) {
                va = ((const uint4*)(A16 + (size_t)grow * DD))[c];
                vh = ((const uint4*)(Xh + (size_t)grow * DD))[c];
            } else {
                va = make_uint4(0, 0, 0, 0);
                vh = va;
            }
            *(uint4*)(sm + GSM_A  + r * 272 + c * 16) = va;
            *(uint4*)(sm + GSM_XH + r * 272 + c * 16) = vh;
        }
        __syncthreads();

        float d[8][4];
#pragma unroll
        for (int i = 0; i < 8; i++)
#pragma unroll
            for (int j = 0; j < 4; j++) d[i][j] = 0.f;

#pragma unroll
        for (int p = 0; p < 2; p++) {
            uint32_t abase = sbase + aoff[p] + a_off;
            uint32_t b_off = sbase + woff[p] + b_rel;
#pragma unroll
            for (int ks = 0; ks < 8; ks++) {
                uint32_t a0, a1, a2, a3;
                asm volatile(
                    "ldmatrix.sync.aligned.m8n8.x4.shared.b16 {%0,%1,%2,%3}, [%4];"
                    : "=r"(a0), "=r"(a1), "=r"(a2), "=r"(a3)
                    : "r"(abase + ks * 32));
                uint32_t b[4][4];
#pragma unroll
                for (int bq = 0; bq < 4; bq++) {
                    asm volatile(
                        "ldmatrix.sync.aligned.m8n8.x4.shared.b16 {%0,%1,%2,%3}, [%4];"
                        : "=r"(b[bq][0]), "=r"(b[bq][1]), "=r"(b[bq][2]), "=r"(b[bq][3])
                        : "r"(b_off + bq * (16 * 272) + ks * 32));
                }
#pragma unroll
                for (int nf = 0; nf < 8; nf++) {
                    uint32_t b0 = b[nf >> 1][(nf & 1) * 2];
                    uint32_t b1 = b[nf >> 1][(nf & 1) * 2 + 1];
                    asm volatile(
                        "mma.sync.aligned.m16n8k16.row.col.f32.f16.f16.f32 "
                        "{%0,%1,%2,%3}, {%4,%5,%6,%7}, {%8,%9}, {%0,%1,%2,%3};"
                        : "+f"(d[nf][0]), "+f"(d[nf][1]), "+f"(d[nf][2]), "+f"(d[nf][3])
                        : "r"(a0), "r"(a1), "r"(a2), "r"(a3), "r"(b0), "r"(b1));
                }
            }
        }

        // Zero the consumed aggregate rows for the next layer's scatter
        if (aggz) {
            uint4 z = make_uint4(0, 0, 0, 0);
            for (int w = tid; w < 64 * 16; w += 256) {
                int r = w >> 4, c = w & 15;
                int grow = row0 + r;
                if (grow < NN) ((uint4*)(aggz + (size_t)grow * DD))[c] = z;
            }
        }

        // Epilogue straight from fragments
        int er0 = row0 + rw * 16 + (lane >> 2);
#pragma unroll
        for (int nf = 0; nf < 8; nf++) {
            int c = cw * 64 + nf * 8 + 2 * (lane & 3);
            float bz0 = __ldg(&bias[c]);
            float bz1 = __ldg(&bias[c + 1]);
#pragma unroll
            for (int half = 0; half < 2; half++) {
                int grow = er0 + half * 8;
                if (grow < NN) {
                    float v0 = d[nf][half * 2 + 0] + bz0;
                    float v1 = d[nf][half * 2 + 1] + bz1;
                    if (relu) { v0 = fmaxf(v0, 0.f); v1 = fmaxf(v1, 0.f); }
                    if (out32)
                        *(float2*)(out32 + (size_t)grow * DD + c) = make_float2(v0, v1);
                    if (outh) {
                        __half2 hh = __floats2half2_rn(v0, v1);
                        *(__half2*)(outh + (size_t)grow * DD + c) = hh;
                    }
                }
            }
        }
    }
}

// ---------------------------------------------------------------------------
// Launch
// ---------------------------------------------------------------------------
extern "C" void kernel_launch(void* const* d_in, const int* in_sizes, int n_in,
                              void* d_out, int out_size) {
    const float* x       = (const float*)d_in[0];
    const int*   ei      = (const int*)d_in[1];   // int32 (JAX x64 disabled)
    const float* W1_rel  = (const float*)d_in[2];
    const float* b1_rel  = (const float*)d_in[3];
    const float* W1_root = (const float*)d_in[4];
    const float* W2_rel  = (const float*)d_in[5];
    const float* b2_rel  = (const float*)d_in[6];
    const float* W2_root = (const float*)d_in[7];
    float*       out     = (float*)d_out;

    __half *agg16, *xh, *hh, *wth;
    cudaGetSymbolAddress((void**)&agg16, g_agg16);
    cudaGetSymbolAddress((void**)&xh, g_xh);
    cudaGetSymbolAddress((void**)&hh, g_hh);
    cudaGetSymbolAddress((void**)&wth, g_wth);

    cudaFuncSetAttribute(gemm_mma_kernel,
                         cudaFuncAttributeMaxDynamicSharedMemorySize,
                         (int)GSMEM);

    const int pgrid = (PREP_TOT + 255) / 256;
    const int nwarp = (EE + EPW - 1) / EPW;
    const int sgrid = (nwarp * 32 + 255) / 256;

    const int WM = 128 * PST;

    // Fused prep: zero agg16 + x->xh + weight transpose (once per launch)
    prep_kernel<<<pgrid, 256>>>((const float4*)x, W1_rel, W1_root,
                                W2_rel, W2_root,
                                (uint4*)agg16, (uint2*)xh, wth);

    // Layer 1: A=agg(xh), X=xh; emits hh; zeroes agg16 for layer 2
    scatter16_kernel<<<sgrid, 256>>>(xh, ei, agg16);
    gemm_mma_kernel<<<GGRID, 256, GSMEM>>>(agg16, agg16, xh,
                                           wth + 0 * WM, wth + 1 * WM,
                                           b1_rel, nullptr, hh, 1);

    // Layer 2: A=agg(hh), X=hh; emits fp32 out
    scatter16_kernel<<<sgrid, 256>>>(hh, ei, agg16);
    gemm_mma_kernel<<<GGRID, 256, GSMEM>>>(agg16, nullptr, hh,
                                           wth + 2 * WM, wth + 3 * WM,
                                           b2_rel, out, nullptr, 0);
}

// round 17
// speedup vs baseline: 1.0466x; 1.0466x over previous
#include <cuda_runtime.h>
#include <cuda_fp16.h>
#include <cstdint>

// Problem constants
#define NN 50000
#define DD 128
#define EE 625000
#define PST 136          // padded row stride in halves (272 B) for ldmatrix

// Scratch (allocation-free rule: __device__ globals)
__device__ __half g_agg16[(size_t)NN * DD];
__device__ __half g_xh[(size_t)NN * DD];
__device__ __half g_hh[(size_t)NN * DD];
// Transposed fp16 weights, padded [128 n][PST k]:
// 0=W1_rel 1=W1_root 2=W2_rel 3=W2_root
__device__ __half g_wth[4 * 128 * PST];

// ---------------------------------------------------------------------------
// Fused prep: zero agg16 | x->xh fp16 convert | weight transpose->fp16.
// ---------------------------------------------------------------------------
#define PREP_Z   (NN * DD / 8)
#define PREP_C   (NN * DD / 4)
#define PREP_W   (4 * 128 * 128)
#define PREP_TOT (PREP_Z + PREP_C + PREP_W)

__global__ void prep_kernel(const float4* __restrict__ x,
                            const float* __restrict__ w0,
                            const float* __restrict__ w1,
                            const float* __restrict__ w2,
                            const float* __restrict__ w3,
                            uint4* __restrict__ aggz,
                            uint2* __restrict__ xh,
                            __half* __restrict__ wth) {
    int i = blockIdx.x * blockDim.x + threadIdx.x;
    if (i < PREP_Z) {
        aggz[i] = make_uint4(0, 0, 0, 0);
    } else if (i < PREP_Z + PREP_C) {
        int j = i - PREP_Z;
        float4 v = x[j];
        __half2 a = __floats2half2_rn(v.x, v.y);
        __half2 b = __floats2half2_rn(v.z, v.w);
        xh[j] = make_uint2(*(unsigned*)&a, *(unsigned*)&b);
    } else if (i < PREP_TOT) {
        int g = i - PREP_Z - PREP_C;
        int m = g >> 14, e = g & 16383;
        int n = e >> 7, k = e & 127;
        const float* W = (m == 0) ? w0 : (m == 1) ? w1 : (m == 2) ? w2 : w3;
        wth[m * 128 * PST + n * PST + k] = __float2half_rn(W[k * 128 + n]);
    }
}

// ---------------------------------------------------------------------------
// fp16 scatter-aggregate: half-warp per edge, 128-bit REDs (proven R12
// shape: EPW=8, regs 32, occ ~83%).
// ---------------------------------------------------------------------------
#define EPW 8
__global__ void scatter16_kernel(const __half* __restrict__ feat,
                                 const int* __restrict__ ei,
                                 __half* __restrict__ agg) {
    int gw = (blockIdx.x * blockDim.x + threadIdx.x) >> 5;
    int lane = threadIdx.x & 31;
    int half = lane >> 4;
    int hl = lane & 15;
    int e0 = gw * EPW;
    if (e0 >= EE) return;

    uint4 v[EPW / 2];
    int d[EPW / 2];
#pragma unroll
    for (int t = 0; t < EPW / 2; t++) {
        int e = e0 + 2 * t + half;
        if (e < EE) {
            int s = __ldg(&ei[e]);
            d[t] = __ldg(&ei[EE + e]);
            v[t] = ((const uint4*)(feat + (size_t)s * DD))[hl];
        }
    }
#pragma unroll
    for (int t = 0; t < EPW / 2; t++) {
        int e = e0 + 2 * t + half;
        if (e < EE) {
            const __half* dp = agg + (size_t)d[t] * DD + hl * 8;
            asm volatile("red.global.add.noftz.v4.f16x2 [%0], {%1, %2, %3, %4};"
                         :: "l"(dp), "r"(v[t].x), "r"(v[t].y),
                            "r"(v[t].z), "r"(v[t].w)
                         : "memory");
        }
    }
}

// ---------------------------------------------------------------------------
// Persistent MMA GEMM: out = act( agg@Wrel + X@Wroot + bias ).
// 2 fp16 HMMA passes: (agg, Wrel) (Xh, Wroot).
// grid = 296 (2 CTAs/SM); weights staged ONCE per CTA; loop over 64-row
// tiles. Smem: A(17408)+X(17408)+W0(34816)+W1(34816) = 104448 B.
// ---------------------------------------------------------------------------
#define GSM_A   0
#define GSM_XH  17408
#define GSM_W0  34816
#define GSM_W1  69632
#define GSMEM   104448
#define NTILES  ((NN + 63) / 64)     // 782
#define GGRID   296

__device__ __forceinline__ uint32_t smem_u32(const void* p) {
    uint32_t a;
    asm("{ .reg .u64 t; cvta.to.shared.u64 t, %1; cvt.u32.u64 %0, t; }"
        : "=r"(a) : "l"(p));
    return a;
}

__global__ __launch_bounds__(256, 2)
void gemm_mma_kernel(const __half* __restrict__ A16,
                     __half* __restrict__ aggz,       // to zero (or null)
                     const __half* __restrict__ Xh,
                     const __half* __restrict__ wth_rel,
                     const __half* __restrict__ wth_root,
                     const float* __restrict__ bias,
                     float* __restrict__ out32,       // fp32 out (or null)
                     __half* __restrict__ outh,       // fp16 out (or null)
                     int relu) {
    extern __shared__ char sm[];
    uint32_t sbase = smem_u32(sm);
    int tid = threadIdx.x, wid = tid >> 5, lane = tid & 31;

    // Stage both W tiles ONCE per CTA
    for (int i = tid; i < 2176; i += 256) {
        ((uint4*)(sm + GSM_W0))[i] = ((const uint4*)wth_rel)[i];
        ((uint4*)(sm + GSM_W1))[i] = ((const uint4*)wth_root)[i];
    }

    int rw = wid & 3;       // row-block (4 x 16 rows = 64)
    int cw = wid >> 2;      // col-block (2 x 64 cols = 128)

    int a_row  = rw * 16 + ((lane >> 3) & 1) * 8 + (lane & 7);
    int a_koff = (lane >> 4) * 8;
    uint32_t a_off = (uint32_t)(a_row * 272 + a_koff * 2);
    int b_mat = lane >> 3;
    int b_line = cw * 64 + ((b_mat >> 1) & 1) * 8 + (lane & 7);
    int b_koff = (b_mat & 1) * 8;
    uint32_t b_rel = (uint32_t)(b_line * 272 + b_koff * 2);

    const uint32_t aoff[2] = {GSM_A, GSM_XH};
    const uint32_t woff[2] = {GSM_W0, GSM_W1};

    for (int bt = blockIdx.x; bt < NTILES; bt += GGRID) {
        int row0 = bt * 64;

        __syncthreads();   // prior tile's readers done (and W ready on iter 0)
        // Stage A/X tiles: [64][PST]h (row pad 272 B)
        for (int w = tid; w < 64 * 16; w += 256) {
            int r = w >> 4, c = w & 15;
            int grow = row0 + r;
            uint4 va, vh;
            if (grow < NN) {
                va = ((const uint4*)(A16 + (size_t)grow * DD))[c];
                vh = ((const uint4*)(Xh + (size_t)grow * DD))[c];
            } else {
                va = make_uint4(0, 0, 0, 0);
                vh = va;
            }
            *(uint4*)(sm + GSM_A  + r * 272 + c * 16) = va;
            *(uint4*)(sm + GSM_XH + r * 272 + c * 16) = vh;
        }
        __syncthreads();

        float d[8][4];
#pragma unroll
        for (int i = 0; i < 8; i++)
#pragma unroll
            for (int j = 0; j < 4; j++) d[i][j] = 0.f;

#pragma unroll
        for (int p = 0; p < 2; p++) {
            uint32_t abase = sbase + aoff[p] + a_off;
            uint32_t b_off = sbase + woff[p] + b_rel;
#pragma unroll
            for (int ks = 0; ks < 8; ks++) {
                uint32_t a0, a1, a2, a3;
                asm volatile(
                    "ldmatrix.sync.aligned.m8n8.x4.shared.b16 {%0,%1,%2,%3}, [%4];"
                    : "=r"(a0), "=r"(a1), "=r"(a2), "=r"(a3)
                    : "r"(abase + ks * 32));
                uint32_t b[4][4];
#pragma unroll
                for (int bq = 0; bq < 4; bq++) {
                    asm volatile(
                        "ldmatrix.sync.aligned.m8n8.x4.shared.b16 {%0,%1,%2,%3}, [%4];"
                        : "=r"(b[bq][0]), "=r"(b[bq][1]), "=r"(b[bq][2]), "=r"(b[bq][3])
                        : "r"(b_off + bq * (16 * 272) + ks * 32));
                }
#pragma unroll
                for (int nf = 0; nf < 8; nf++) {
                    uint32_t b0 = b[nf >> 1][(nf & 1) * 2];
                    uint32_t b1 = b[nf >> 1][(nf & 1) * 2 + 1];
                    asm volatile(
                        "mma.sync.aligned.m16n8k16.row.col.f32.f16.f16.f32 "
                        "{%0,%1,%2,%3}, {%4,%5,%6,%7}, {%8,%9}, {%0,%1,%2,%3};"
                        : "+f"(d[nf][0]), "+f"(d[nf][1]), "+f"(d[nf][2]), "+f"(d[nf][3])
                        : "r"(a0), "r"(a1), "r"(a2), "r"(a3), "r"(b0), "r"(b1));
                }
            }
        }

        // Zero the consumed aggregate rows early (streaming stores drain
        // under the epilogue math below)
        if (aggz) {
            uint4 z = make_uint4(0, 0, 0, 0);
            for (int w = tid; w < 64 * 16; w += 256) {
                int r = w >> 4, c = w & 15;
                int grow = row0 + r;
                if (grow < NN) ((uint4*)(aggz + (size_t)grow * DD))[c] = z;
            }
        }

        // Epilogue straight from fragments
        int er0 = row0 + rw * 16 + (lane >> 2);
#pragma unroll
        for (int nf = 0; nf < 8; nf++) {
            int c = cw * 64 + nf * 8 + 2 * (lane & 3);
            float bz0 = __ldg(&bias[c]);
            float bz1 = __ldg(&bias[c + 1]);
#pragma unroll
            for (int half = 0; half < 2; half++) {
                int grow = er0 + half * 8;
                if (grow < NN) {
                    float v0 = d[nf][half * 2 + 0] + bz0;
                    float v1 = d[nf][half * 2 + 1] + bz1;
                    if (relu) { v0 = fmaxf(v0, 0.f); v1 = fmaxf(v1, 0.f); }
                    if (out32)
                        *(float2*)(out32 + (size_t)grow * DD + c) = make_float2(v0, v1);
                    if (outh) {
                        __half2 hh = __floats2half2_rn(v0, v1);
                        *(__half2*)(outh + (size_t)grow * DD + c) = hh;
                    }
                }
            }
        }
    }
}

// ---------------------------------------------------------------------------
// Launch
// ---------------------------------------------------------------------------
extern "C" void kernel_launch(void* const* d_in, const int* in_sizes, int n_in,
                              void* d_out, int out_size) {
    const float* x       = (const float*)d_in[0];
    const int*   ei      = (const int*)d_in[1];   // int32 (JAX x64 disabled)
    const float* W1_rel  = (const float*)d_in[2];
    const float* b1_rel  = (const float*)d_in[3];
    const float* W1_root = (const float*)d_in[4];
    const float* W2_rel  = (const float*)d_in[5];
    const float* b2_rel  = (const float*)d_in[6];
    const float* W2_root = (const float*)d_in[7];
    float*       out     = (float*)d_out;

    __half *agg16, *xh, *hh, *wth;
    cudaGetSymbolAddress((void**)&agg16, g_agg16);
    cudaGetSymbolAddress((void**)&xh, g_xh);
    cudaGetSymbolAddress((void**)&hh, g_hh);
    cudaGetSymbolAddress((void**)&wth, g_wth);

    cudaFuncSetAttribute(gemm_mma_kernel,
                         cudaFuncAttributeMaxDynamicSharedMemorySize,
                         (int)GSMEM);

    const int pgrid = (PREP_TOT + 255) / 256;
    const int nwarp = (EE + EPW - 1) / EPW;
    const int sgrid = (nwarp * 32 + 255) / 256;

    const int WM = 128 * PST;

    // Fused prep: zero agg16 + x->xh + weight transpose (once per launch)
    prep_kernel<<<pgrid, 256>>>((const float4*)x, W1_rel, W1_root,
                                W2_rel, W2_root,
                                (uint4*)agg16, (uint2*)xh, wth);

    // Layer 1: A=agg(xh), X=xh; emits hh; zeroes agg16 for layer 2
    scatter16_kernel<<<sgrid, 256>>>(xh, ei, agg16);
    gemm_mma_kernel<<<GGRID, 256, GSMEM>>>(agg16, agg16, xh,
                                           wth + 0 * WM, wth + 1 * WM,
                                           b1_rel, nullptr, hh, 1);

    // Layer 2: A=agg(hh), X=hh; emits fp32 out
    scatter16_kernel<<<sgrid, 256>>>(hh, ei, agg16);
    gemm_mma_kernel<<<GGRID, 256, GSMEM>>>(agg16, nullptr, hh,
                                           wth + 2 * WM, wth + 3 * WM,
                                           b2_rel, out, nullptr, 0);
}